// round 3
// baseline (speedup 1.0000x reference)
#include <cuda_runtime.h>
#include <math.h>

// Problem constants
#define BB    64
#define TT    128
#define IDIM  4096
#define HH    1024
#define FOURH 4096
#define K0    2048   // layer-0 step GEMM K: [h | c]
#define K1    3072   // layer-1 step GEMM K: [ha | h1 | c1]
#define KSPLIT 4

// ---------------- device scratch (static: no allocation in kernel_launch) ----------------
__device__ float g_XZ0[(size_t)TT * BB * FOURH];   // precomputed x@Wx0^T + b0, layout [t][b][h*4+g]
__device__ float g_Wx0r[(size_t)FOURH * IDIM];     // Wx0 repacked, row n=h*4+g
__device__ float g_W0r[(size_t)FOURH * K0];        // [Uh0 | Vc0(zero for gate c)] interleaved rows
__device__ float g_W1r[(size_t)FOURH * K1];        // [Wx1 | Uh1 | Vc1(zero for gate c)]
__device__ float g_b0r[FOURH];
__device__ float g_b1r[FOURH];
__device__ float g_S0[2][BB * K0];                 // double-buffered [h | c] per batch row
__device__ float g_S1[2][BB * K1];                 // double-buffered [ha | h1 | c1]
__device__ float g_P[KSPLIT][BB * FOURH];          // split-K partial sums

// ---------------- repack kernels ----------------
__global__ void repack_wx0(const float* __restrict__ Wx0, const float* __restrict__ b0) {
    int n = blockIdx.x;            // 0..4095
    int g = n & 3, h = n >> 2;
    const float* src = Wx0 + (size_t)(g * HH + h) * IDIM;
    float* dst = g_Wx0r + (size_t)n * IDIM;
    for (int i = threadIdx.x; i < IDIM; i += blockDim.x) dst[i] = src[i];
    if (threadIdx.x == 0) g_b0r[n] = b0[g * HH + h];
}

__global__ void repack_w0(const float* __restrict__ Uh0, const float* __restrict__ Vc0) {
    int n = blockIdx.x;
    int g = n & 3, h = n >> 2;
    float* dst = g_W0r + (size_t)n * K0;
    const float* u = Uh0 + (size_t)(g * HH + h) * HH;
    for (int k = threadIdx.x; k < HH; k += blockDim.x) dst[k] = u[k];
    int vg = (g == 0) ? 0 : (g == 1) ? 1 : (g == 3) ? 2 : -1;   // gates [i,f,c,o]; Vc stacks [i,f,o]
    if (vg >= 0) {
        const float* v = Vc0 + (size_t)(vg * HH + h) * HH;
        for (int k = threadIdx.x; k < HH; k += blockDim.x) dst[HH + k] = v[k];
    } else {
        for (int k = threadIdx.x; k < HH; k += blockDim.x) dst[HH + k] = 0.0f;
    }
}

__global__ void repack_w1(const float* __restrict__ Wx1, const float* __restrict__ Uh1,
                          const float* __restrict__ Vc1, const float* __restrict__ b1) {
    int n = blockIdx.x;
    int g = n & 3, h = n >> 2;
    float* dst = g_W1r + (size_t)n * K1;
    const float* wx = Wx1 + (size_t)(g * HH + h) * HH;
    const float* uh = Uh1 + (size_t)(g * HH + h) * HH;
    for (int k = threadIdx.x; k < HH; k += blockDim.x) dst[k] = wx[k];
    for (int k = threadIdx.x; k < HH; k += blockDim.x) dst[HH + k] = uh[k];
    int vg = (g == 0) ? 0 : (g == 1) ? 1 : (g == 3) ? 2 : -1;
    if (vg >= 0) {
        const float* v = Vc1 + (size_t)(vg * HH + h) * HH;
        for (int k = threadIdx.x; k < HH; k += blockDim.x) dst[2 * HH + k] = v[k];
    } else {
        for (int k = threadIdx.x; k < HH; k += blockDim.x) dst[2 * HH + k] = 0.0f;
    }
    if (threadIdx.x == 0) g_b1r[n] = b1[g * HH + h];
}

__global__ void init_state(const float* __restrict__ h0, const float* __restrict__ c0) {
    int idx = blockIdx.x * blockDim.x + threadIdx.x;   // B*H = 65536 threads
    int b = idx >> 10, h = idx & 1023;
    g_S0[0][b * K0 + h]            = h0[b * HH + h];                 // layer 0 h
    g_S0[0][b * K0 + HH + h]       = c0[b * HH + h];                 // layer 0 c
    g_S1[0][b * K1 + HH + h]       = h0[BB * HH + b * HH + h];       // layer 1 h
    g_S1[0][b * K1 + 2 * HH + h]   = c0[BB * HH + b * HH + h];       // layer 1 c
    g_S1[0][b * K1 + h]            = 0.0f;                           // ha slot (overwritten)
}

// ---------------- phase A: XZ0 = x @ Wx0r^T + b0r ----------------
// M=8192 (r = b*T+t), N=4096, K=4096. 128x128x16 tiles, 256 threads, 8x8 per thread.
__global__ __launch_bounds__(256) void gemm_xz(const float* __restrict__ X) {
    __shared__ float As[16][128];
    __shared__ float Bs[16][128];
    const int tid = threadIdx.x;
    const int tx = tid & 15, ty = tid >> 4;              // 16 x 16 thread grid
    const int m0 = blockIdx.y * 128, n0 = blockIdx.x * 128;
    float acc[8][8];
#pragma unroll
    for (int i = 0; i < 8; i++)
#pragma unroll
        for (int j = 0; j < 8; j++) acc[i][j] = 0.0f;

    const float* Aptr = X + (size_t)m0 * IDIM;
    const float* Wptr = g_Wx0r + (size_t)n0 * IDIM;

    for (int k0 = 0; k0 < IDIM; k0 += 16) {
#pragma unroll
        for (int i = 0; i < 2; i++) {
            int id = tid + i * 256;
            int row = id >> 2, c4 = (id & 3) << 2;
            float4 va = *(const float4*)(Aptr + (size_t)row * IDIM + k0 + c4);
            As[c4 + 0][row] = va.x; As[c4 + 1][row] = va.y;
            As[c4 + 2][row] = va.z; As[c4 + 3][row] = va.w;
            float4 vb = *(const float4*)(Wptr + (size_t)row * IDIM + k0 + c4);
            Bs[c4 + 0][row] = vb.x; Bs[c4 + 1][row] = vb.y;
            Bs[c4 + 2][row] = vb.z; Bs[c4 + 3][row] = vb.w;
        }
        __syncthreads();
#pragma unroll
        for (int k = 0; k < 16; k++) {
            float a[8], w[8];
            *(float4*)(a)     = *(const float4*)&As[k][ty * 8];
            *(float4*)(a + 4) = *(const float4*)&As[k][ty * 8 + 4];
            *(float4*)(w)     = *(const float4*)&Bs[k][tx * 8];
            *(float4*)(w + 4) = *(const float4*)&Bs[k][tx * 8 + 4];
#pragma unroll
            for (int i = 0; i < 8; i++)
#pragma unroll
                for (int j = 0; j < 8; j++)
                    acc[i][j] = fmaf(a[i], w[j], acc[i][j]);
        }
        __syncthreads();
    }

    float bias[8];
#pragma unroll
    for (int j = 0; j < 8; j++) bias[j] = g_b0r[n0 + tx * 8 + j];
#pragma unroll
    for (int i = 0; i < 8; i++) {
        int r = m0 + ty * 8 + i;
        int t = r & (TT - 1), b = r >> 7;                // r = b*T + t
        float* dst = g_XZ0 + ((size_t)(t * BB + b) << 12) + n0 + tx * 8;
#pragma unroll
        for (int j = 0; j < 8; j++) dst[j] = acc[i][j] + bias[j];
    }
}

// ---------------- recurrent step GEMM (split-K partials) ----------------
// M=64 (batch), N=4096, K = K0 or K1. 64x64 tiles, 128 threads, 8x4 per thread.
template <int WHICH>
__global__ __launch_bounds__(128) void step_gemm(int p) {
    constexpr int K   = WHICH ? K1 : K0;
    constexpr int SEG = K / KSPLIT;                       // 512 or 768
    const float* __restrict__ A = WHICH ? g_S1[p] : g_S0[p];
    const float* __restrict__ W = WHICH ? g_W1r : g_W0r;

    __shared__ float As[16][64];
    __shared__ float Ws[16][64];
    const int tid = threadIdx.x;
    const int tx = tid & 15, ty = tid >> 4;               // tx: 16 n-cols groups, ty: 8 m-row groups
    const int n0 = blockIdx.x * 64;
    const int kbeg = blockIdx.y * SEG;

    float acc[8][4];
#pragma unroll
    for (int i = 0; i < 8; i++)
#pragma unroll
        for (int j = 0; j < 4; j++) acc[i][j] = 0.0f;

    for (int kk = 0; kk < SEG; kk += 16) {
#pragma unroll
        for (int i = 0; i < 2; i++) {
            int id = tid + i * 128;
            int row = id >> 2, c4 = (id & 3) << 2;
            float4 va = *(const float4*)(A + (size_t)row * K + kbeg + kk + c4);
            As[c4 + 0][row] = va.x; As[c4 + 1][row] = va.y;
            As[c4 + 2][row] = va.z; As[c4 + 3][row] = va.w;
            float4 vw = *(const float4*)(W + (size_t)(n0 + row) * K + kbeg + kk + c4);
            Ws[c4 + 0][row] = vw.x; Ws[c4 + 1][row] = vw.y;
            Ws[c4 + 2][row] = vw.z; Ws[c4 + 3][row] = vw.w;
        }
        __syncthreads();
#pragma unroll
        for (int k = 0; k < 16; k++) {
            float a[8], w[4];
            *(float4*)(a)     = *(const float4*)&As[k][ty * 8];
            *(float4*)(a + 4) = *(const float4*)&As[k][ty * 8 + 4];
            *(float4*)(w)     = *(const float4*)&Ws[k][tx * 4];
#pragma unroll
            for (int i = 0; i < 8; i++)
#pragma unroll
                for (int j = 0; j < 4; j++)
                    acc[i][j] = fmaf(a[i], w[j], acc[i][j]);
        }
        __syncthreads();
    }

    float* dst = g_P[blockIdx.y];
#pragma unroll
    for (int i = 0; i < 8; i++) {
        int b = ty * 8 + i;
        *(float4*)&dst[((size_t)b << 12) + n0 + tx * 4] =
            make_float4(acc[i][0], acc[i][1], acc[i][2], acc[i][3]);
    }
}

// ---------------- epilogues ----------------
__device__ __forceinline__ float sig_(float z) { return 1.0f / (1.0f + expf(-z)); }

__global__ __launch_bounds__(256) void epi0(int t, int p) {
    int idx = blockIdx.x * 256 + threadIdx.x;             // B*H
    int b = idx >> 10, h = idx & 1023;
    int nb = h << 2;
    float4 z = *(const float4*)&g_XZ0[((size_t)(t * BB + b) << 12) + nb];
#pragma unroll
    for (int ks = 0; ks < KSPLIT; ks++) {
        float4 pp = *(const float4*)&g_P[ks][((size_t)b << 12) + nb];
        z.x += pp.x; z.y += pp.y; z.z += pp.z; z.w += pp.w;
    }
    float c_old = g_S0[p][b * K0 + HH + h];
    float ig = sig_(z.x), fg = sig_(z.y), gg = tanhf(z.z), og = sig_(z.w);
    float cn = fg * c_old + ig * gg;
    float hn = og * tanhf(cn);
    g_S0[p ^ 1][b * K0 + h]      = hn;
    g_S0[p ^ 1][b * K0 + HH + h] = cn;
    g_S1[p][b * K1 + h]          = hn;                    // ha feeds layer 1 this step
}

__global__ __launch_bounds__(256) void epi1(int t, int p, float* __restrict__ out) {
    int idx = blockIdx.x * 256 + threadIdx.x;
    int b = idx >> 10, h = idx & 1023;
    int nb = h << 2;
    float4 z = *(const float4*)&g_b1r[nb];
#pragma unroll
    for (int ks = 0; ks < KSPLIT; ks++) {
        float4 pp = *(const float4*)&g_P[ks][((size_t)b << 12) + nb];
        z.x += pp.x; z.y += pp.y; z.z += pp.z; z.w += pp.w;
    }
    float c_old = g_S1[p][b * K1 + 2 * HH + h];
    float ig = sig_(z.x), fg = sig_(z.y), gg = tanhf(z.z), og = sig_(z.w);
    float cn = fg * c_old + ig * gg;
    float hn = og * tanhf(cn);
    g_S1[p ^ 1][b * K1 + HH + h]     = hn;
    g_S1[p ^ 1][b * K1 + 2 * HH + h] = cn;
    out[((size_t)b * TT + t) * HH + h] = hn;
}

__global__ __launch_bounds__(256) void finalize(float* __restrict__ out) {
    int idx = blockIdx.x * 256 + threadIdx.x;             // B*H
    int b = idx >> 10, h = idx & 1023;
    float* hn = out + (size_t)BB * TT * HH;               // h_n after output
    float* cn = hn + 2 * BB * HH;                         // c_n after h_n
    // T=128 is even -> final states live in buffer parity 0
    hn[b * HH + h]            = g_S0[0][b * K0 + h];
    cn[b * HH + h]            = g_S0[0][b * K0 + HH + h];
    hn[BB * HH + b * HH + h]  = g_S1[0][b * K1 + HH + h];
    cn[BB * HH + b * HH + h]  = g_S1[0][b * K1 + 2 * HH + h];
}

// ---------------- launch ----------------
extern "C" void kernel_launch(void* const* d_in, const int* in_sizes, int n_in,
                              void* d_out, int out_size) {
    (void)in_sizes; (void)n_in; (void)out_size;
    const float* x   = (const float*)d_in[0];
    const float* h0  = (const float*)d_in[1];
    const float* c0  = (const float*)d_in[2];
    const float* Wx0 = (const float*)d_in[3];
    const float* Uh0 = (const float*)d_in[4];
    const float* Vc0 = (const float*)d_in[5];
    const float* b0  = (const float*)d_in[6];
    const float* Wx1 = (const float*)d_in[7];
    const float* Uh1 = (const float*)d_in[8];
    const float* Vc1 = (const float*)d_in[9];
    const float* b1  = (const float*)d_in[10];
    float* out = (float*)d_out;

    repack_wx0<<<FOURH, 256>>>(Wx0, b0);
    repack_w0 <<<FOURH, 256>>>(Uh0, Vc0);
    repack_w1 <<<FOURH, 256>>>(Wx1, Uh1, Vc1, b1);
    init_state<<<(BB * HH) / 256, 256>>>(h0, c0);

    gemm_xz<<<dim3(FOURH / 128, (BB * TT) / 128), 256>>>(x);

    for (int t = 0; t < TT; t++) {
        int p = t & 1;
        step_gemm<0><<<dim3(FOURH / 64, KSPLIT), 128>>>(p);
        epi0<<<(BB * HH) / 256, 256>>>(t, p);
        step_gemm<1><<<dim3(FOURH / 64, KSPLIT), 128>>>(p);
        epi1<<<(BB * HH) / 256, 256>>>(t, p, out);
    }

    finalize<<<(BB * HH) / 256, 256>>>(out);
}

// round 5
// speedup vs baseline: 1.7686x; 1.7686x over previous
#include <cuda_runtime.h>
#include <cuda_bf16.h>
#include <math.h>
#include <stdint.h>

// Problem constants
#define BB    64
#define TT    128
#define IDIM  4096
#define HH    1024
#define FOURH 4096
#define K0    2048   // layer-0 step GEMM K: [h | c]
#define K1    3072   // layer-1 step GEMM K: [ha | h1 | c1]
#define KSPLIT 4

// ---------------- device scratch ----------------
__device__ float g_XZ0[(size_t)TT * BB * FOURH];          // x@Wx0^T + b0, layout [t][b][h*4+g]
__device__ __nv_bfloat16 g_Axh[(size_t)BB * TT * IDIM];   // x hi
__device__ __nv_bfloat16 g_Axl[(size_t)BB * TT * IDIM];   // x lo
__device__ __nv_bfloat16 g_Bwh[(size_t)FOURH * IDIM];     // Wx0 repacked hi (row n=h*4+g)
__device__ __nv_bfloat16 g_Bwl[(size_t)FOURH * IDIM];
__device__ __nv_bfloat16 g_W0h[(size_t)FOURH * K0];       // [Uh0 | Vc0(0 for gate c)] hi
__device__ __nv_bfloat16 g_W0l[(size_t)FOURH * K0];
__device__ __nv_bfloat16 g_W1h[(size_t)FOURH * K1];       // [Wx1 | Uh1 | Vc1(0 for gate c)] hi
__device__ __nv_bfloat16 g_W1l[(size_t)FOURH * K1];
__device__ float g_b0r[FOURH];
__device__ float g_b1r[FOURH];
__device__ __nv_bfloat16 g_S0h[BB * K0];                  // layer-0 GEMM input [h | c] hi
__device__ __nv_bfloat16 g_S0l[BB * K0];
__device__ __nv_bfloat16 g_S1h[BB * K1];                  // layer-1 GEMM input [ha | h1 | c1] hi
__device__ __nv_bfloat16 g_S1l[BB * K1];
__device__ float g_C0[BB * HH];                           // fp32 cell states
__device__ float g_C1[BB * HH];
__device__ float g_P[KSPLIT][BB * FOURH];                 // split-K partials

// ---------------- helpers ----------------
__device__ __forceinline__ uint32_t smem_u32(const void* p) {
    uint32_t a;
    asm("{ .reg .u64 t; cvta.to.shared.u64 t, %1; cvt.u32.u64 %0, t; }" : "=r"(a) : "l"(p));
    return a;
}
__device__ __forceinline__ void ldsm_x4(uint32_t* r, uint32_t a) {
    asm volatile("ldmatrix.sync.aligned.m8n8.x4.shared.b16 {%0,%1,%2,%3}, [%4];"
                 : "=r"(r[0]), "=r"(r[1]), "=r"(r[2]), "=r"(r[3]) : "r"(a));
}
__device__ __forceinline__ void ldsm_x2(uint32_t* r, uint32_t a) {
    asm volatile("ldmatrix.sync.aligned.m8n8.x2.shared.b16 {%0,%1}, [%2];"
                 : "=r"(r[0]), "=r"(r[1]) : "r"(a));
}
__device__ __forceinline__ void mma_bf16(float* d, const uint32_t* a, const uint32_t* b) {
    asm volatile(
        "mma.sync.aligned.m16n8k16.row.col.f32.bf16.bf16.f32 "
        "{%0,%1,%2,%3}, {%4,%5,%6,%7}, {%8,%9}, {%0,%1,%2,%3};"
        : "+f"(d[0]), "+f"(d[1]), "+f"(d[2]), "+f"(d[3])
        : "r"(a[0]), "r"(a[1]), "r"(a[2]), "r"(a[3]), "r"(b[0]), "r"(b[1]));
}
__device__ __forceinline__ void split_bf(float v, __nv_bfloat16& h, __nv_bfloat16& l) {
    h = __float2bfloat16_rn(v);
    l = __float2bfloat16_rn(v - __bfloat162float(h));
}
__device__ __forceinline__ float sig_(float z) { return 1.0f / (1.0f + expf(-z)); }

// ---------------- conversion / repack ----------------
__global__ void conv_x(const float* __restrict__ x) {
    size_t i = ((size_t)blockIdx.x * 256 + threadIdx.x) * 4;
    float4 v = *(const float4*)(x + i);
    union { __nv_bfloat16 b[4]; uint2 u; } ph, pl;
    split_bf(v.x, ph.b[0], pl.b[0]); split_bf(v.y, ph.b[1], pl.b[1]);
    split_bf(v.z, ph.b[2], pl.b[2]); split_bf(v.w, ph.b[3], pl.b[3]);
    *(uint2*)(g_Axh + i) = ph.u;
    *(uint2*)(g_Axl + i) = pl.u;
}

__global__ void repack_wx0b(const float* __restrict__ Wx0, const float* __restrict__ b0) {
    int n = blockIdx.x;            // n = h*4+g
    int g = n & 3, h = n >> 2;
    const float* src = Wx0 + (size_t)(g * HH + h) * IDIM;
    __nv_bfloat16* dh = g_Bwh + (size_t)n * IDIM;
    __nv_bfloat16* dl = g_Bwl + (size_t)n * IDIM;
    for (int i = threadIdx.x; i < IDIM; i += blockDim.x) {
        __nv_bfloat16 hh, ll; split_bf(src[i], hh, ll);
        dh[i] = hh; dl[i] = ll;
    }
    if (threadIdx.x == 0) g_b0r[n] = b0[g * HH + h];
}

__global__ void repack_w0(const float* __restrict__ Uh0, const float* __restrict__ Vc0) {
    int n = blockIdx.x;
    int g = n & 3, h = n >> 2;
    __nv_bfloat16* dh = g_W0h + (size_t)n * K0;
    __nv_bfloat16* dl = g_W0l + (size_t)n * K0;
    const float* u = Uh0 + (size_t)(g * HH + h) * HH;
    for (int k = threadIdx.x; k < HH; k += blockDim.x) {
        __nv_bfloat16 hh, ll; split_bf(u[k], hh, ll);
        dh[k] = hh; dl[k] = ll;
    }
    int vg = (g == 0) ? 0 : (g == 1) ? 1 : (g == 3) ? 2 : -1;   // Vc stacks [i,f,o]
    if (vg >= 0) {
        const float* v = Vc0 + (size_t)(vg * HH + h) * HH;
        for (int k = threadIdx.x; k < HH; k += blockDim.x) {
            __nv_bfloat16 hh, ll; split_bf(v[k], hh, ll);
            dh[HH + k] = hh; dl[HH + k] = ll;
        }
    } else {
        for (int k = threadIdx.x; k < HH; k += blockDim.x) {
            dh[HH + k] = __float2bfloat16(0.0f);
            dl[HH + k] = __float2bfloat16(0.0f);
        }
    }
}

__global__ void repack_w1(const float* __restrict__ Wx1, const float* __restrict__ Uh1,
                          const float* __restrict__ Vc1, const float* __restrict__ b1) {
    int n = blockIdx.x;
    int g = n & 3, h = n >> 2;
    __nv_bfloat16* dh = g_W1h + (size_t)n * K1;
    __nv_bfloat16* dl = g_W1l + (size_t)n * K1;
    const float* wx = Wx1 + (size_t)(g * HH + h) * HH;
    const float* uh = Uh1 + (size_t)(g * HH + h) * HH;
    for (int k = threadIdx.x; k < HH; k += blockDim.x) {
        __nv_bfloat16 hh, ll; split_bf(wx[k], hh, ll);
        dh[k] = hh; dl[k] = ll;
        split_bf(uh[k], hh, ll);
        dh[HH + k] = hh; dl[HH + k] = ll;
    }
    int vg = (g == 0) ? 0 : (g == 1) ? 1 : (g == 3) ? 2 : -1;
    if (vg >= 0) {
        const float* v = Vc1 + (size_t)(vg * HH + h) * HH;
        for (int k = threadIdx.x; k < HH; k += blockDim.x) {
            __nv_bfloat16 hh, ll; split_bf(v[k], hh, ll);
            dh[2 * HH + k] = hh; dl[2 * HH + k] = ll;
        }
    } else {
        for (int k = threadIdx.x; k < HH; k += blockDim.x) {
            dh[2 * HH + k] = __float2bfloat16(0.0f);
            dl[2 * HH + k] = __float2bfloat16(0.0f);
        }
    }
    if (threadIdx.x == 0) g_b1r[n] = b1[g * HH + h];
}

__global__ void init_state(const float* __restrict__ h0, const float* __restrict__ c0) {
    int idx = blockIdx.x * blockDim.x + threadIdx.x;   // B*H
    int b = idx >> 10, h = idx & 1023;
    __nv_bfloat16 hh, ll;
    float v;
    v = h0[b * HH + h];
    split_bf(v, hh, ll); g_S0h[b * K0 + h] = hh; g_S0l[b * K0 + h] = ll;
    v = c0[b * HH + h];
    g_C0[idx] = v;
    split_bf(v, hh, ll); g_S0h[b * K0 + HH + h] = hh; g_S0l[b * K0 + HH + h] = ll;
    v = h0[BB * HH + b * HH + h];
    split_bf(v, hh, ll); g_S1h[b * K1 + HH + h] = hh; g_S1l[b * K1 + HH + h] = ll;
    v = c0[BB * HH + b * HH + h];
    g_C1[idx] = v;
    split_bf(v, hh, ll); g_S1h[b * K1 + 2 * HH + h] = hh; g_S1l[b * K1 + 2 * HH + h] = ll;
    g_S1h[b * K1 + h] = __float2bfloat16(0.0f);
    g_S1l[b * K1 + h] = __float2bfloat16(0.0f);
}

// ---------------- phase A: XZ0 = x @ Wx0^T + b0, bf16-split mma.sync ----------------
// CTA tile 128x128, k-chunk 32. smem rows: 64B data, stride 80B (conflict-free ldmatrix).
#define PAS 80
__global__ __launch_bounds__(256) void gemm_xz_mma() {
    __shared__ __align__(16) unsigned char sm[4 * 128 * PAS];   // Ah | Al | Bh | Bl
    const int tid = threadIdx.x;
    const int w = tid >> 5, l = tid & 31;
    const int wm = w & 3, wn = w >> 2;                  // 4 M-quads x 2 N-halves
    const int m0 = blockIdx.y * 128, n0 = blockIdx.x * 128;
    const uint32_t sb = smem_u32(sm);
    const uint32_t OFF = 128 * PAS;

    float acc[2][8][4];
#pragma unroll
    for (int a = 0; a < 2; a++)
#pragma unroll
        for (int b = 0; b < 8; b++)
#pragma unroll
            for (int c = 0; c < 4; c++) acc[a][b][c] = 0.0f;

    for (int kc = 0; kc < IDIM / 32; kc++) {
        const int k0 = kc * 32;
        for (int i = tid; i < 512; i += 256) {
            int r = i >> 2, sg = (i & 3) * 16;
            uint32_t d = (uint32_t)(r * PAS + sg);
            const char* ah = (const char*)(g_Axh + (size_t)(m0 + r) * IDIM + k0);
            const char* al = (const char*)(g_Axl + (size_t)(m0 + r) * IDIM + k0);
            const char* bh = (const char*)(g_Bwh + (size_t)(n0 + r) * IDIM + k0);
            const char* bl = (const char*)(g_Bwl + (size_t)(n0 + r) * IDIM + k0);
            *(uint4*)(sm + d)           = *(const uint4*)(ah + sg);
            *(uint4*)(sm + OFF + d)     = *(const uint4*)(al + sg);
            *(uint4*)(sm + 2 * OFF + d) = *(const uint4*)(bh + sg);
            *(uint4*)(sm + 3 * OFF + d) = *(const uint4*)(bl + sg);
        }
        __syncthreads();
#pragma unroll
        for (int ks = 0; ks < 2; ks++) {
            const int kb = ks * 32;                      // byte offset within row
            uint32_t ah[2][4], al[2][4];
#pragma unroll
            for (int mt = 0; mt < 2; mt++) {
                uint32_t ra = sb + (uint32_t)((wm * 32 + mt * 16 + (l & 15)) * PAS + kb + ((l >> 4) << 4));
                ldsm_x4(ah[mt], ra);
                ldsm_x4(al[mt], ra + OFF);
            }
#pragma unroll
            for (int nt = 0; nt < 8; nt++) {
                uint32_t rb = sb + 2 * OFF +
                    (uint32_t)((wn * 64 + nt * 8 + (l & 7)) * PAS + kb + (((l >> 3) & 1) << 4));
                uint32_t bh[2], bl[2];
                ldsm_x2(bh, rb);
                ldsm_x2(bl, rb + OFF);
#pragma unroll
                for (int mt = 0; mt < 2; mt++) {
                    mma_bf16(acc[mt][nt], ah[mt], bh);
                    mma_bf16(acc[mt][nt], ah[mt], bl);
                    mma_bf16(acc[mt][nt], al[mt], bh);
                }
            }
        }
        __syncthreads();
    }

    const int r0 = l >> 2, cp = (l & 3) * 2;
#pragma unroll
    for (int mt = 0; mt < 2; mt++)
#pragma unroll
        for (int half = 0; half < 2; half++) {
            int gm = m0 + wm * 32 + mt * 16 + r0 + half * 8;
            int t = gm & (TT - 1), b = gm >> 7;          // gm = b*T + t
            float* dst = g_XZ0 + ((size_t)(t * BB + b) << 12);
#pragma unroll
            for (int nt = 0; nt < 8; nt++) {
                int gc = n0 + wn * 64 + nt * 8 + cp;
                float2 v;
                v.x = acc[mt][nt][half * 2 + 0] + g_b0r[gc];
                v.y = acc[mt][nt][half * 2 + 1] + g_b0r[gc + 1];
                *(float2*)(dst + gc) = v;
            }
        }
}

// ---------------- recurrent step GEMM: bf16-split mma.sync, split-K partials ----------------
// CTA tile 64x64, 4 warps (warp = m16 x n64), k-chunk 32.
template <int WHICH>
__global__ __launch_bounds__(128) void step_gemm_mma() {
    constexpr int K   = WHICH ? K1 : K0;
    constexpr int SEG = K / KSPLIT;                      // 512 or 768
    const __nv_bfloat16* __restrict__ Ash = WHICH ? g_S1h : g_S0h;
    const __nv_bfloat16* __restrict__ Asl = WHICH ? g_S1l : g_S0l;
    const __nv_bfloat16* __restrict__ Wh  = WHICH ? g_W1h : g_W0h;
    const __nv_bfloat16* __restrict__ Wl  = WHICH ? g_W1l : g_W0l;

    __shared__ __align__(16) unsigned char sm[4 * 64 * PAS];    // Ah | Al | Bh | Bl
    const int tid = threadIdx.x;
    const int w = tid >> 5, l = tid & 31;
    const int n0 = blockIdx.x * 64;
    const int kbeg = blockIdx.y * SEG;
    const uint32_t sb = smem_u32(sm);
    const uint32_t OFF = 64 * PAS;

    float acc[8][4];
#pragma unroll
    for (int b = 0; b < 8; b++)
#pragma unroll
        for (int c = 0; c < 4; c++) acc[b][c] = 0.0f;

    for (int kc = 0; kc < SEG / 32; kc++) {
        const int k0 = kbeg + kc * 32;
        for (int i = tid; i < 256; i += 128) {
            int r = i >> 2, sg = (i & 3) * 16;
            uint32_t d = (uint32_t)(r * PAS + sg);
            const char* ah = (const char*)(Ash + (size_t)r * K + k0);
            const char* al = (const char*)(Asl + (size_t)r * K + k0);
            const char* bh = (const char*)(Wh + (size_t)(n0 + r) * K + k0);
            const char* bl = (const char*)(Wl + (size_t)(n0 + r) * K + k0);
            *(uint4*)(sm + d)           = *(const uint4*)(ah + sg);
            *(uint4*)(sm + OFF + d)     = *(const uint4*)(al + sg);
            *(uint4*)(sm + 2 * OFF + d) = *(const uint4*)(bh + sg);
            *(uint4*)(sm + 3 * OFF + d) = *(const uint4*)(bl + sg);
        }
        __syncthreads();
#pragma unroll
        for (int ks = 0; ks < 2; ks++) {
            const int kb = ks * 32;
            uint32_t ah[4], al[4];
            uint32_t ra = sb + (uint32_t)((w * 16 + (l & 15)) * PAS + kb + ((l >> 4) << 4));
            ldsm_x4(ah, ra);
            ldsm_x4(al, ra + OFF);
#pragma unroll
            for (int nt = 0; nt < 8; nt++) {
                uint32_t rb = sb + 2 * OFF +
                    (uint32_t)((nt * 8 + (l & 7)) * PAS + kb + (((l >> 3) & 1) << 4));
                uint32_t bh[2], bl[2];
                ldsm_x2(bh, rb);
                ldsm_x2(bl, rb + OFF);
                mma_bf16(acc[nt], ah, bh);
                mma_bf16(acc[nt], ah, bl);
                mma_bf16(acc[nt], al, bh);
            }
        }
        __syncthreads();
    }

    float* dst = g_P[blockIdx.y];
    const int r0 = l >> 2, cp = (l & 3) * 2;
#pragma unroll
    for (int half = 0; half < 2; half++) {
        int b = w * 16 + r0 + half * 8;
#pragma unroll
        for (int nt = 0; nt < 8; nt++) {
            int gc = n0 + nt * 8 + cp;
            float2 v;
            v.x = acc[nt][half * 2 + 0];
            v.y = acc[nt][half * 2 + 1];
            *(float2*)(dst + ((size_t)b << 12) + gc) = v;
        }
    }
}

// ---------------- epilogues ----------------
__global__ __launch_bounds__(256) void epi0(int t) {
    int idx = blockIdx.x * 256 + threadIdx.x;            // B*H
    int b = idx >> 10, h = idx & 1023;
    int nb = h << 2;
    float4 z = *(const float4*)&g_XZ0[((size_t)(t * BB + b) << 12) + nb];
#pragma unroll
    for (int ks = 0; ks < KSPLIT; ks++) {
        float4 pp = *(const float4*)&g_P[ks][((size_t)b << 12) + nb];
        z.x += pp.x; z.y += pp.y; z.z += pp.z; z.w += pp.w;
    }
    float c_old = g_C0[idx];
    float ig = sig_(z.x), fg = sig_(z.y), gg = tanhf(z.z), og = sig_(z.w);
    float cn = fg * c_old + ig * gg;
    float hn = og * tanhf(cn);
    g_C0[idx] = cn;
    __nv_bfloat16 hh, ll;
    split_bf(hn, hh, ll);
    g_S0h[b * K0 + h] = hh;          g_S0l[b * K0 + h] = ll;
    g_S1h[b * K1 + h] = hh;          g_S1l[b * K1 + h] = ll;      // ha feeds layer 1
    split_bf(cn, hh, ll);
    g_S0h[b * K0 + HH + h] = hh;     g_S0l[b * K0 + HH + h] = ll;
}

__global__ __launch_bounds__(256) void epi1(int t, float* __restrict__ out) {
    int idx = blockIdx.x * 256 + threadIdx.x;
    int b = idx >> 10, h = idx & 1023;
    int nb = h << 2;
    float4 z = *(const float4*)&g_b1r[nb];
#pragma unroll
    for (int ks = 0; ks < KSPLIT; ks++) {
        float4 pp = *(const float4*)&g_P[ks][((size_t)b << 12) + nb];
        z.x += pp.x; z.y += pp.y; z.z += pp.z; z.w += pp.w;
    }
    float c_old = g_C1[idx];
    float ig = sig_(z.x), fg = sig_(z.y), gg = tanhf(z.z), og = sig_(z.w);
    float cn = fg * c_old + ig * gg;
    float hn = og * tanhf(cn);
    g_C1[idx] = cn;
    __nv_bfloat16 hh, ll;
    split_bf(hn, hh, ll);
    g_S1h[b * K1 + HH + h] = hh;     g_S1l[b * K1 + HH + h] = ll;
    split_bf(cn, hh, ll);
    g_S1h[b * K1 + 2 * HH + h] = hh; g_S1l[b * K1 + 2 * HH + h] = ll;
    out[((size_t)b * TT + t) * HH + h] = hn;
}

__global__ __launch_bounds__(256) void finalize(float* __restrict__ out) {
    int idx = blockIdx.x * 256 + threadIdx.x;            // B*H
    int b = idx >> 10, h = idx & 1023;
    float* hn = out + (size_t)BB * TT * HH;              // h_n after output
    float* cn = hn + 2 * BB * HH;                        // c_n after h_n
    hn[b * HH + h] = __bfloat162float(g_S0h[b * K0 + h]) + __bfloat162float(g_S0l[b * K0 + h]);
    cn[b * HH + h] = g_C0[idx];
    hn[BB * HH + b * HH + h] =
        __bfloat162float(g_S1h[b * K1 + HH + h]) + __bfloat162float(g_S1l[b * K1 + HH + h]);
    cn[BB * HH + b * HH + h] = g_C1[idx];
}

// ---------------- launch ----------------
extern "C" void kernel_launch(void* const* d_in, const int* in_sizes, int n_in,
                              void* d_out, int out_size) {
    (void)in_sizes; (void)n_in; (void)out_size;
    const float* x   = (const float*)d_in[0];
    const float* h0  = (const float*)d_in[1];
    const float* c0  = (const float*)d_in[2];
    const float* Wx0 = (const float*)d_in[3];
    const float* Uh0 = (const float*)d_in[4];
    const float* Vc0 = (const float*)d_in[5];
    const float* b0  = (const float*)d_in[6];
    const float* Wx1 = (const float*)d_in[7];
    const float* Uh1 = (const float*)d_in[8];
    const float* Vc1 = (const float*)d_in[9];
    const float* b1  = (const float*)d_in[10];
    float* out = (float*)d_out;

    conv_x     <<<(BB * TT * IDIM) / (4 * 256), 256>>>(x);
    repack_wx0b<<<FOURH, 256>>>(Wx0, b0);
    repack_w0  <<<FOURH, 256>>>(Uh0, Vc0);
    repack_w1  <<<FOURH, 256>>>(Wx1, Uh1, Vc1, b1);
    init_state <<<(BB * HH) / 256, 256>>>(h0, c0);

    gemm_xz_mma<<<dim3(FOURH / 128, (BB * TT) / 128), 256>>>();

    for (int t = 0; t < TT; t++) {
        step_gemm_mma<0><<<dim3(FOURH / 64, KSPLIT), 128>>>();
        epi0<<<(BB * HH) / 256, 256>>>(t);
        step_gemm_mma<1><<<dim3(FOURH / 64, KSPLIT), 128>>>();
        epi1<<<(BB * HH) / 256, 256>>>(t, out);
    }

    finalize<<<(BB * HH) / 256, 256>>>(out);
}

// round 6
// speedup vs baseline: 1.7980x; 1.0166x over previous
#include <cuda_runtime.h>
#include <cuda_bf16.h>
#include <math.h>
#include <stdint.h>

// Problem constants
#define BB    64
#define TT    128
#define IDIM  4096
#define HH    1024
#define FOURH 4096
#define K0    2048   // layer-0 step GEMM K: [h | c]
#define K1    3072   // layer-1 step GEMM K: [ha | h1 | c1]
#define KSPLIT 4
#define GRID_N 128   // persistent-loop grid (<148 SMs -> wave-1 co-resident)

// ---------------- device scratch ----------------
__device__ float g_XZ0[(size_t)TT * BB * FOURH];          // x@Wx0^T + b0, layout [t][b][h*4+g]
__device__ __nv_bfloat16 g_Axh[(size_t)BB * TT * IDIM];   // x hi
__device__ __nv_bfloat16 g_Axl[(size_t)BB * TT * IDIM];   // x lo
__device__ __nv_bfloat16 g_Bwh[(size_t)FOURH * IDIM];     // Wx0 repacked hi (row n=h*4+g)
__device__ __nv_bfloat16 g_Bwl[(size_t)FOURH * IDIM];
__device__ __nv_bfloat16 g_W0h[(size_t)FOURH * K0];       // [Uh0 | Vc0(0 for gate c)] hi
__device__ __nv_bfloat16 g_W0l[(size_t)FOURH * K0];
__device__ __nv_bfloat16 g_W1h[(size_t)FOURH * K1];       // [Wx1 | Uh1 | Vc1(0 for gate c)] hi
__device__ __nv_bfloat16 g_W1l[(size_t)FOURH * K1];
__device__ float g_b0r[FOURH];
__device__ float g_b1r[FOURH];
__device__ __nv_bfloat16 g_S0h[BB * K0];                  // layer-0 GEMM input [h | c] hi
__device__ __nv_bfloat16 g_S0l[BB * K0];
__device__ __nv_bfloat16 g_S1h[BB * K1];                  // layer-1 GEMM input [ha | h1 | c1] hi
__device__ __nv_bfloat16 g_S1l[BB * K1];
__device__ float g_C0[BB * HH];                           // fp32 cell states (loop keeps in regs)
__device__ float g_C1[BB * HH];
__device__ float g_P[KSPLIT][BB * FOURH];                 // split-K partials
__device__ unsigned int g_bar;                            // grid barrier counter

// ---------------- helpers ----------------
__device__ __forceinline__ uint32_t smem_u32(const void* p) {
    uint32_t a;
    asm("{ .reg .u64 t; cvta.to.shared.u64 t, %1; cvt.u32.u64 %0, t; }" : "=r"(a) : "l"(p));
    return a;
}
__device__ __forceinline__ void ldsm_x4(uint32_t* r, uint32_t a) {
    asm volatile("ldmatrix.sync.aligned.m8n8.x4.shared.b16 {%0,%1,%2,%3}, [%4];"
                 : "=r"(r[0]), "=r"(r[1]), "=r"(r[2]), "=r"(r[3]) : "r"(a));
}
__device__ __forceinline__ void ldsm_x2(uint32_t* r, uint32_t a) {
    asm volatile("ldmatrix.sync.aligned.m8n8.x2.shared.b16 {%0,%1}, [%2];"
                 : "=r"(r[0]), "=r"(r[1]) : "r"(a));
}
__device__ __forceinline__ void mma_bf16(float* d, const uint32_t* a, const uint32_t* b) {
    asm volatile(
        "mma.sync.aligned.m16n8k16.row.col.f32.bf16.bf16.f32 "
        "{%0,%1,%2,%3}, {%4,%5,%6,%7}, {%8,%9}, {%0,%1,%2,%3};"
        : "+f"(d[0]), "+f"(d[1]), "+f"(d[2]), "+f"(d[3])
        : "r"(a[0]), "r"(a[1]), "r"(a[2]), "r"(a[3]), "r"(b[0]), "r"(b[1]));
}
__device__ __forceinline__ void split_bf(float v, __nv_bfloat16& h, __nv_bfloat16& l) {
    h = __float2bfloat16_rn(v);
    l = __float2bfloat16_rn(v - __bfloat162float(h));
}
__device__ __forceinline__ float sig_(float z) { return 1.0f / (1.0f + expf(-z)); }

// grid-wide barrier: release/acquire via atomic counter in L2
__device__ __forceinline__ void grid_sync(unsigned int target) {
    __syncthreads();
    if (threadIdx.x == 0) {
        __threadfence();
        atomicAdd(&g_bar, 1u);
        while (__ldcg(&g_bar) < target) __nanosleep(32);
        __threadfence();
    }
    __syncthreads();
}

// ---------------- conversion / repack ----------------
__global__ void conv_x(const float* __restrict__ x) {
    size_t i = ((size_t)blockIdx.x * 256 + threadIdx.x) * 4;
    float4 v = *(const float4*)(x + i);
    union { __nv_bfloat16 b[4]; uint2 u; } ph, pl;
    split_bf(v.x, ph.b[0], pl.b[0]); split_bf(v.y, ph.b[1], pl.b[1]);
    split_bf(v.z, ph.b[2], pl.b[2]); split_bf(v.w, ph.b[3], pl.b[3]);
    *(uint2*)(g_Axh + i) = ph.u;
    *(uint2*)(g_Axl + i) = pl.u;
}

__global__ void repack_wx0b(const float* __restrict__ Wx0, const float* __restrict__ b0) {
    int n = blockIdx.x;            // n = h*4+g
    int g = n & 3, h = n >> 2;
    const float* src = Wx0 + (size_t)(g * HH + h) * IDIM;
    __nv_bfloat16* dh = g_Bwh + (size_t)n * IDIM;
    __nv_bfloat16* dl = g_Bwl + (size_t)n * IDIM;
    for (int i = threadIdx.x; i < IDIM; i += blockDim.x) {
        __nv_bfloat16 hh, ll; split_bf(src[i], hh, ll);
        dh[i] = hh; dl[i] = ll;
    }
    if (threadIdx.x == 0) g_b0r[n] = b0[g * HH + h];
}

__global__ void repack_w0(const float* __restrict__ Uh0, const float* __restrict__ Vc0) {
    int n = blockIdx.x;
    int g = n & 3, h = n >> 2;
    __nv_bfloat16* dh = g_W0h + (size_t)n * K0;
    __nv_bfloat16* dl = g_W0l + (size_t)n * K0;
    const float* u = Uh0 + (size_t)(g * HH + h) * HH;
    for (int k = threadIdx.x; k < HH; k += blockDim.x) {
        __nv_bfloat16 hh, ll; split_bf(u[k], hh, ll);
        dh[k] = hh; dl[k] = ll;
    }
    int vg = (g == 0) ? 0 : (g == 1) ? 1 : (g == 3) ? 2 : -1;   // Vc stacks [i,f,o]
    if (vg >= 0) {
        const float* v = Vc0 + (size_t)(vg * HH + h) * HH;
        for (int k = threadIdx.x; k < HH; k += blockDim.x) {
            __nv_bfloat16 hh, ll; split_bf(v[k], hh, ll);
            dh[HH + k] = hh; dl[HH + k] = ll;
        }
    } else {
        for (int k = threadIdx.x; k < HH; k += blockDim.x) {
            dh[HH + k] = __float2bfloat16(0.0f);
            dl[HH + k] = __float2bfloat16(0.0f);
        }
    }
}

__global__ void repack_w1(const float* __restrict__ Wx1, const float* __restrict__ Uh1,
                          const float* __restrict__ Vc1, const float* __restrict__ b1) {
    int n = blockIdx.x;
    int g = n & 3, h = n >> 2;
    __nv_bfloat16* dh = g_W1h + (size_t)n * K1;
    __nv_bfloat16* dl = g_W1l + (size_t)n * K1;
    const float* wx = Wx1 + (size_t)(g * HH + h) * HH;
    const float* uh = Uh1 + (size_t)(g * HH + h) * HH;
    for (int k = threadIdx.x; k < HH; k += blockDim.x) {
        __nv_bfloat16 hh, ll; split_bf(wx[k], hh, ll);
        dh[k] = hh; dl[k] = ll;
        split_bf(uh[k], hh, ll);
        dh[HH + k] = hh; dl[HH + k] = ll;
    }
    int vg = (g == 0) ? 0 : (g == 1) ? 1 : (g == 3) ? 2 : -1;
    if (vg >= 0) {
        const float* v = Vc1 + (size_t)(vg * HH + h) * HH;
        for (int k = threadIdx.x; k < HH; k += blockDim.x) {
            __nv_bfloat16 hh, ll; split_bf(v[k], hh, ll);
            dh[2 * HH + k] = hh; dl[2 * HH + k] = ll;
        }
    } else {
        for (int k = threadIdx.x; k < HH; k += blockDim.x) {
            dh[2 * HH + k] = __float2bfloat16(0.0f);
            dl[2 * HH + k] = __float2bfloat16(0.0f);
        }
    }
    if (threadIdx.x == 0) g_b1r[n] = b1[g * HH + h];
}

__global__ void init_state(const float* __restrict__ h0, const float* __restrict__ c0) {
    int idx = blockIdx.x * blockDim.x + threadIdx.x;   // B*H
    if (idx == 0) g_bar = 0u;                          // reset grid barrier each launch
    int b = idx >> 10, h = idx & 1023;
    __nv_bfloat16 hh, ll;
    float v;
    v = h0[b * HH + h];
    split_bf(v, hh, ll); g_S0h[b * K0 + h] = hh; g_S0l[b * K0 + h] = ll;
    v = c0[b * HH + h];
    g_C0[idx] = v;
    split_bf(v, hh, ll); g_S0h[b * K0 + HH + h] = hh; g_S0l[b * K0 + HH + h] = ll;
    v = h0[BB * HH + b * HH + h];
    split_bf(v, hh, ll); g_S1h[b * K1 + HH + h] = hh; g_S1l[b * K1 + HH + h] = ll;
    v = c0[BB * HH + b * HH + h];
    g_C1[idx] = v;
    split_bf(v, hh, ll); g_S1h[b * K1 + 2 * HH + h] = hh; g_S1l[b * K1 + 2 * HH + h] = ll;
    g_S1h[b * K1 + h] = __float2bfloat16(0.0f);
    g_S1l[b * K1 + h] = __float2bfloat16(0.0f);
}

// ---------------- phase A: XZ0 = x @ Wx0^T + b0, bf16-split mma.sync ----------------
#define PAS 80
__global__ __launch_bounds__(256) void gemm_xz_mma() {
    __shared__ __align__(16) unsigned char sm[4 * 128 * PAS];   // Ah | Al | Bh | Bl
    const int tid = threadIdx.x;
    const int w = tid >> 5, l = tid & 31;
    const int wm = w & 3, wn = w >> 2;
    const int m0 = blockIdx.y * 128, n0 = blockIdx.x * 128;
    const uint32_t sb = smem_u32(sm);
    const uint32_t OFF = 128 * PAS;

    float acc[2][8][4];
#pragma unroll
    for (int a = 0; a < 2; a++)
#pragma unroll
        for (int b = 0; b < 8; b++)
#pragma unroll
            for (int c = 0; c < 4; c++) acc[a][b][c] = 0.0f;

    for (int kc = 0; kc < IDIM / 32; kc++) {
        const int k0 = kc * 32;
        for (int i = tid; i < 512; i += 256) {
            int r = i >> 2, sg = (i & 3) * 16;
            uint32_t d = (uint32_t)(r * PAS + sg);
            const char* ah = (const char*)(g_Axh + (size_t)(m0 + r) * IDIM + k0);
            const char* al = (const char*)(g_Axl + (size_t)(m0 + r) * IDIM + k0);
            const char* bh = (const char*)(g_Bwh + (size_t)(n0 + r) * IDIM + k0);
            const char* bl = (const char*)(g_Bwl + (size_t)(n0 + r) * IDIM + k0);
            *(uint4*)(sm + d)           = *(const uint4*)(ah + sg);
            *(uint4*)(sm + OFF + d)     = *(const uint4*)(al + sg);
            *(uint4*)(sm + 2 * OFF + d) = *(const uint4*)(bh + sg);
            *(uint4*)(sm + 3 * OFF + d) = *(const uint4*)(bl + sg);
        }
        __syncthreads();
#pragma unroll
        for (int ks = 0; ks < 2; ks++) {
            const int kb = ks * 32;
            uint32_t ah[2][4], al[2][4];
#pragma unroll
            for (int mt = 0; mt < 2; mt++) {
                uint32_t ra = sb + (uint32_t)((wm * 32 + mt * 16 + (l & 15)) * PAS + kb + ((l >> 4) << 4));
                ldsm_x4(ah[mt], ra);
                ldsm_x4(al[mt], ra + OFF);
            }
#pragma unroll
            for (int nt = 0; nt < 8; nt++) {
                uint32_t rb = sb + 2 * OFF +
                    (uint32_t)((wn * 64 + nt * 8 + (l & 7)) * PAS + kb + (((l >> 3) & 1) << 4));
                uint32_t bh[2], bl[2];
                ldsm_x2(bh, rb);
                ldsm_x2(bl, rb + OFF);
#pragma unroll
                for (int mt = 0; mt < 2; mt++) {
                    mma_bf16(acc[mt][nt], ah[mt], bh);
                    mma_bf16(acc[mt][nt], ah[mt], bl);
                    mma_bf16(acc[mt][nt], al[mt], bh);
                }
            }
        }
        __syncthreads();
    }

    const int r0 = l >> 2, cp = (l & 3) * 2;
#pragma unroll
    for (int mt = 0; mt < 2; mt++)
#pragma unroll
        for (int half = 0; half < 2; half++) {
            int gm = m0 + wm * 32 + mt * 16 + r0 + half * 8;
            int t = gm & (TT - 1), b = gm >> 7;          // gm = b*T + t
            float* dst = g_XZ0 + ((size_t)(t * BB + b) << 12);
#pragma unroll
            for (int nt = 0; nt < 8; nt++) {
                int gc = n0 + wn * 64 + nt * 8 + cp;
                float2 v;
                v.x = acc[mt][nt][half * 2 + 0] + g_b0r[gc];
                v.y = acc[mt][nt][half * 2 + 1] + g_b0r[gc + 1];
                *(float2*)(dst + gc) = v;
            }
        }
}

// ---------------- persistent recurrent loop ----------------
// Per CTA: n-tile 128 (cta&31), k-segment (cta>>5). 8 warps = 4(M16) x 2(N64).
#define A_OFF (64u * PAS)          // 5120
#define B_OFF (2u * A_OFF)         // 10240
#define B_SZ  (128u * PAS)         // 10240
#define LOOP_SMEM (B_OFF + 2u * B_SZ)   // 30720

template <int WHICH>
__device__ __forceinline__ void gemm_phase(int cta, int tid, unsigned char* sm, uint32_t sb) {
    constexpr int K   = WHICH ? K1 : K0;
    constexpr int SEG = K / KSPLIT;                      // 512 or 768
    const __nv_bfloat16* Ash = WHICH ? g_S1h : g_S0h;
    const __nv_bfloat16* Asl = WHICH ? g_S1l : g_S0l;
    const __nv_bfloat16* Wh  = WHICH ? g_W1h : g_W0h;
    const __nv_bfloat16* Wl  = WHICH ? g_W1l : g_W0l;
    const int w = tid >> 5, l = tid & 31;
    const int wm = w & 3, wn = w >> 2;
    const int n0 = (cta & 31) * 128;
    const int kseg = cta >> 5;
    const int kbeg = kseg * SEG;

    float acc[8][4];
#pragma unroll
    for (int b = 0; b < 8; b++)
#pragma unroll
        for (int c = 0; c < 4; c++) acc[b][c] = 0.0f;

    for (int kc = 0; kc < SEG / 32; kc++) {
        const int k0 = kbeg + kc * 32;
        {   // A tile: 64 rows x 32 cols, hi+lo (state -> L1-bypass loads)
            int r = tid >> 2, sg = (tid & 3) * 16;
            uint32_t d = (uint32_t)(r * PAS + sg);
            *(uint4*)(sm + d) =
                __ldcg((const uint4*)((const char*)(Ash + (size_t)r * K + k0) + sg));
            *(uint4*)(sm + A_OFF + d) =
                __ldcg((const uint4*)((const char*)(Asl + (size_t)r * K + k0) + sg));
        }
        for (int i = tid; i < 512; i += 256) {   // B tile: 128 rows, hi+lo
            int r = i >> 2, sg = (i & 3) * 16;
            uint32_t d = (uint32_t)(r * PAS + sg);
            *(uint4*)(sm + B_OFF + d) =
                *(const uint4*)((const char*)(Wh + (size_t)(n0 + r) * K + k0) + sg);
            *(uint4*)(sm + B_OFF + B_SZ + d) =
                *(const uint4*)((const char*)(Wl + (size_t)(n0 + r) * K + k0) + sg);
        }
        __syncthreads();
#pragma unroll
        for (int ks = 0; ks < 2; ks++) {
            const int kb = ks * 32;
            uint32_t ah[4], al[4];
            uint32_t ra = sb + (uint32_t)((wm * 16 + (l & 15)) * PAS + kb + ((l >> 4) << 4));
            ldsm_x4(ah, ra);
            ldsm_x4(al, ra + A_OFF);
#pragma unroll
            for (int nt = 0; nt < 8; nt++) {
                uint32_t rb = sb + B_OFF +
                    (uint32_t)((wn * 64 + nt * 8 + (l & 7)) * PAS + kb + (((l >> 3) & 1) << 4));
                uint32_t bh[2], bl[2];
                ldsm_x2(bh, rb);
                ldsm_x2(bl, rb + B_SZ);
                mma_bf16(acc[nt], ah, bh);
                mma_bf16(acc[nt], ah, bl);
                mma_bf16(acc[nt], al, bh);
            }
        }
        __syncthreads();
    }

    float* dst = g_P[kseg];
    const int r0 = l >> 2, cp = (l & 3) * 2;
#pragma unroll
    for (int half = 0; half < 2; half++) {
        int b = wm * 16 + r0 + half * 8;
#pragma unroll
        for (int nt = 0; nt < 8; nt++) {
            int gc = n0 + wn * 64 + nt * 8 + cp;
            float2 v;
            v.x = acc[nt][half * 2 + 0];
            v.y = acc[nt][half * 2 + 1];
            *(float2*)(dst + ((size_t)b << 12) + gc) = v;
        }
    }
}

__global__ __launch_bounds__(256) void rnn_loop(float* __restrict__ out) {
    __shared__ __align__(16) unsigned char sm[LOOP_SMEM];
    const int cta = blockIdx.x, tid = threadIdx.x;
    const uint32_t sb = smem_u32(sm);
    const int gthread = cta * 256 + tid;       // 0..32767
    const int idx0 = gthread * 2;              // this thread owns idx0, idx0+1 (same batch b)
    const int b = idx0 >> 10;
    const int h0i = idx0 & 1023;
    float cA[2] = { g_C0[idx0], g_C0[idx0 + 1] };
    float cB[2] = { g_C1[idx0], g_C1[idx0 + 1] };
    float* hn_base = out + (size_t)BB * TT * HH;
    float* cn_base = hn_base + 2 * BB * HH;
    unsigned int seq = 0;

    for (int t = 0; t < TT; t++) {
        gemm_phase<0>(cta, tid, sm, sb);
        grid_sync(++seq * GRID_N);

        // epi0: gates -> new (h,c) for layer 0; feed ha into layer-1 input
#pragma unroll
        for (int j = 0; j < 2; j++) {
            int h = h0i + j, nb = h << 2;
            float4 z = *(const float4*)&g_XZ0[((size_t)(t * BB + b) << 12) + nb];
#pragma unroll
            for (int ks = 0; ks < KSPLIT; ks++) {
                float4 pp = __ldcg((const float4*)&g_P[ks][((size_t)b << 12) + nb]);
                z.x += pp.x; z.y += pp.y; z.z += pp.z; z.w += pp.w;
            }
            float ig = sig_(z.x), fg = sig_(z.y), gg = tanhf(z.z), og = sig_(z.w);
            float cn = fg * cA[j] + ig * gg;
            float hn = og * tanhf(cn);
            cA[j] = cn;
            __nv_bfloat16 hh, ll;
            split_bf(hn, hh, ll);
            g_S0h[b * K0 + h] = hh;      g_S0l[b * K0 + h] = ll;
            g_S1h[b * K1 + h] = hh;      g_S1l[b * K1 + h] = ll;
            split_bf(cn, hh, ll);
            g_S0h[b * K0 + HH + h] = hh; g_S0l[b * K0 + HH + h] = ll;
            if (t == TT - 1) {
                hn_base[b * HH + h] = hn;
                cn_base[b * HH + h] = cn;
            }
        }
        grid_sync(++seq * GRID_N);

        gemm_phase<1>(cta, tid, sm, sb);
        grid_sync(++seq * GRID_N);

        // epi1: layer-1 gates; write output sequence
#pragma unroll
        for (int j = 0; j < 2; j++) {
            int h = h0i + j, nb = h << 2;
            float4 z = *(const float4*)&g_b1r[nb];
#pragma unroll
            for (int ks = 0; ks < KSPLIT; ks++) {
                float4 pp = __ldcg((const float4*)&g_P[ks][((size_t)b << 12) + nb]);
                z.x += pp.x; z.y += pp.y; z.z += pp.z; z.w += pp.w;
            }
            float ig = sig_(z.x), fg = sig_(z.y), gg = tanhf(z.z), og = sig_(z.w);
            float cn = fg * cB[j] + ig * gg;
            float hn = og * tanhf(cn);
            cB[j] = cn;
            __nv_bfloat16 hh, ll;
            split_bf(hn, hh, ll);
            g_S1h[b * K1 + HH + h] = hh;     g_S1l[b * K1 + HH + h] = ll;
            split_bf(cn, hh, ll);
            g_S1h[b * K1 + 2 * HH + h] = hh; g_S1l[b * K1 + 2 * HH + h] = ll;
            out[((size_t)b * TT + t) * HH + h] = hn;
            if (t == TT - 1) {
                hn_base[BB * HH + b * HH + h] = hn;
                cn_base[BB * HH + b * HH + h] = cn;
            }
        }
        grid_sync(++seq * GRID_N);
    }
}

// ---------------- launch ----------------
extern "C" void kernel_launch(void* const* d_in, const int* in_sizes, int n_in,
                              void* d_out, int out_size) {
    (void)in_sizes; (void)n_in; (void)out_size;
    const float* x   = (const float*)d_in[0];
    const float* h0  = (const float*)d_in[1];
    const float* c0  = (const float*)d_in[2];
    const float* Wx0 = (const float*)d_in[3];
    const float* Uh0 = (const float*)d_in[4];
    const float* Vc0 = (const float*)d_in[5];
    const float* b0  = (const float*)d_in[6];
    const float* Wx1 = (const float*)d_in[7];
    const float* Uh1 = (const float*)d_in[8];
    const float* Vc1 = (const float*)d_in[9];
    const float* b1  = (const float*)d_in[10];
    float* out = (float*)d_out;

    conv_x     <<<(BB * TT * IDIM) / (4 * 256), 256>>>(x);
    repack_wx0b<<<FOURH, 256>>>(Wx0, b0);
    repack_w0  <<<FOURH, 256>>>(Uh0, Vc0);
    repack_w1  <<<FOURH, 256>>>(Wx1, Uh1, Vc1, b1);
    init_state <<<(BB * HH) / 256, 256>>>(h0, c0);

    gemm_xz_mma<<<dim3(FOURH / 128, (BB * TT) / 128), 256>>>();

    rnn_loop<<<GRID_N, 256>>>(out);
}

// round 7
// speedup vs baseline: 3.9116x; 2.1756x over previous
#include <cuda_runtime.h>
#include <cuda_bf16.h>
#include <math.h>
#include <stdint.h>

// Problem constants
#define BB    64
#define TT    128
#define IDIM  4096
#define HH    1024
#define FOURH 4096
#define K0    2048
#define K1    3072
#define KSPLIT 4
#define GRID_N 128

// ---------------- device scratch ----------------
// All GEMM operands live in chunk-tiled, pre-swizzled layouts:
//   tile = [rows][128B], 16B-group g of row r stored at (g ^ (r&7)).
//   A raw cp.async.bulk of a tile yields an SW128-swizzled smem tile.
__device__ __align__(128) float g_XZ0[(size_t)TT * BB * FOURH];   // [t][b][h*4+g]
__device__ __align__(128) __nv_bfloat16 g_Axh[(size_t)BB * TT * IDIM]; // [mblk64][kc64][128][128B]
__device__ __align__(128) __nv_bfloat16 g_Axl[(size_t)BB * TT * IDIM];
__device__ __align__(128) __nv_bfloat16 g_Bwh[(size_t)FOURH * IDIM];   // [nblk32][kc64][128][128B]
__device__ __align__(128) __nv_bfloat16 g_Bwl[(size_t)FOURH * IDIM];
__device__ __align__(128) __nv_bfloat16 g_W0h[(size_t)FOURH * K0];     // [nblk32][kc32][128][128B]
__device__ __align__(128) __nv_bfloat16 g_W0l[(size_t)FOURH * K0];
__device__ __align__(128) __nv_bfloat16 g_W1h[(size_t)FOURH * K1];     // [nblk32][kc48][128][128B]
__device__ __align__(128) __nv_bfloat16 g_W1l[(size_t)FOURH * K1];
__device__ float g_b0r[FOURH];
__device__ float g_b1r[FOURH];
__device__ __align__(128) __nv_bfloat16 g_S0h[BB * K0];                // [kc32][64][128B]
__device__ __align__(128) __nv_bfloat16 g_S0l[BB * K0];
__device__ __align__(128) __nv_bfloat16 g_S1h[BB * K1];                // [kc48][64][128B]
__device__ __align__(128) __nv_bfloat16 g_S1l[BB * K1];
__device__ float g_C0[BB * HH];
__device__ float g_C1[BB * HH];
__device__ float g_P[KSPLIT][BB * FOURH];
__device__ unsigned int g_bar;

// swizzled byte offsets into chunk-tiled layouts
#define AX_OFF(r, k)  ( (((size_t)(((r) >> 7) * 64 + ((k) >> 6))) << 14) + (size_t)(((r) & 127) << 7) + (size_t)(((((k) & 63) * 2) ^ (((r) & 7) << 4))) )
#define BW_OFF(n, k)  ( (((size_t)(((n) >> 7) * 64 + ((k) >> 6))) << 14) + (size_t)(((n) & 127) << 7) + (size_t)(((((k) & 63) * 2) ^ (((n) & 7) << 4))) )
#define W0_OFF(n, k)  ( (((size_t)(((n) >> 7) * 32 + ((k) >> 6))) << 14) + (size_t)(((n) & 127) << 7) + (size_t)(((((k) & 63) * 2) ^ (((n) & 7) << 4))) )
#define W1_OFF(n, k)  ( (((size_t)(((n) >> 7) * 48 + ((k) >> 6))) << 14) + (size_t)(((n) & 127) << 7) + (size_t)(((((k) & 63) * 2) ^ (((n) & 7) << 4))) )
#define ST_OFF(k, b)  ( (((size_t)((k) >> 6)) << 13) + (size_t)((b) << 7) + (size_t)(((((k) & 63) * 2) ^ (((b) & 7) << 4))) )

// ---------------- PTX helpers ----------------
__device__ __forceinline__ uint32_t smem_u32(const void* p) {
    uint32_t a;
    asm("{ .reg .u64 t; cvta.to.shared.u64 t, %1; cvt.u32.u64 %0, t; }" : "=r"(a) : "l"(p));
    return a;
}
__device__ __forceinline__ void mbar_init(uint32_t mbar, uint32_t cnt) {
    asm volatile("mbarrier.init.shared.b64 [%0], %1;" :: "r"(mbar), "r"(cnt) : "memory");
}
__device__ __forceinline__ void mbar_expect(uint32_t mbar, uint32_t bytes) {
    asm volatile("mbarrier.arrive.expect_tx.shared.b64 _, [%0], %1;"
                 :: "r"(mbar), "r"(bytes) : "memory");
}
__device__ __forceinline__ void mbar_wait(uint32_t mbar, uint32_t parity) {
    asm volatile(
        "{\n\t.reg .pred P;\n"
        "WL%=:\n\t"
        "mbarrier.try_wait.parity.shared.b64 P, [%0], %1;\n\t"
        "@P bra.uni WD%=;\n\t"
        "bra.uni WL%=;\n"
        "WD%=:\n\t}"
        :: "r"(mbar), "r"(parity) : "memory");
}
__device__ __forceinline__ void bulk_cp(uint32_t dst, const void* src, uint32_t bytes, uint32_t mbar) {
    asm volatile("cp.async.bulk.shared::cta.global.mbarrier::complete_tx::bytes [%0], [%1], %2, [%3];"
                 :: "r"(dst), "l"(src), "r"(bytes), "r"(mbar) : "memory");
}
__device__ __forceinline__ void ldsm_x4(uint32_t* r, uint32_t a) {
    asm volatile("ldmatrix.sync.aligned.m8n8.x4.shared.b16 {%0,%1,%2,%3}, [%4];"
                 : "=r"(r[0]), "=r"(r[1]), "=r"(r[2]), "=r"(r[3]) : "r"(a));
}
__device__ __forceinline__ void ldsm_x2(uint32_t* r, uint32_t a) {
    asm volatile("ldmatrix.sync.aligned.m8n8.x2.shared.b16 {%0,%1}, [%2];"
                 : "=r"(r[0]), "=r"(r[1]) : "r"(a));
}
__device__ __forceinline__ void mma_bf16(float* d, const uint32_t* a, const uint32_t* b) {
    asm volatile(
        "mma.sync.aligned.m16n8k16.row.col.f32.bf16.bf16.f32 "
        "{%0,%1,%2,%3}, {%4,%5,%6,%7}, {%8,%9}, {%0,%1,%2,%3};"
        : "+f"(d[0]), "+f"(d[1]), "+f"(d[2]), "+f"(d[3])
        : "r"(a[0]), "r"(a[1]), "r"(a[2]), "r"(a[3]), "r"(b[0]), "r"(b[1]));
}
__device__ __forceinline__ void split_bf(float v, __nv_bfloat16& h, __nv_bfloat16& l) {
    h = __float2bfloat16_rn(v);
    l = __float2bfloat16_rn(v - __bfloat162float(h));
}
__device__ __forceinline__ uint32_t pack_bf2(__nv_bfloat16 a, __nv_bfloat16 b) {
    union { __nv_bfloat16 h[2]; uint32_t u; } t;
    t.h[0] = a; t.h[1] = b;
    return t.u;
}
__device__ __forceinline__ float sig_(float z) { return 1.0f / (1.0f + expf(-z)); }

__device__ __forceinline__ void grid_sync(unsigned int target) {
    asm volatile("fence.proxy.async;" ::: "memory");
    __syncthreads();
    if (threadIdx.x == 0) {
        __threadfence();
        atomicAdd(&g_bar, 1u);
        while (__ldcg(&g_bar) < target) __nanosleep(32);
        __threadfence();
    }
    __syncthreads();
}

// ---------------- conversion / repack ----------------
__global__ void conv_x(const float* __restrict__ x) {
    size_t gid = (size_t)blockIdx.x * 256 + threadIdx.x;
    size_t i0 = gid * 4;
    float4 v = *(const float4*)(x + i0);
    union { __nv_bfloat16 b[4]; uint2 u; } ph, pl;
    split_bf(v.x, ph.b[0], pl.b[0]); split_bf(v.y, ph.b[1], pl.b[1]);
    split_bf(v.z, ph.b[2], pl.b[2]); split_bf(v.w, ph.b[3], pl.b[3]);
    int r = (int)(i0 >> 12), k = (int)(i0 & 4095);
    size_t off = AX_OFF(r, k);
    *(uint2*)((char*)g_Axh + off) = ph.u;
    *(uint2*)((char*)g_Axl + off) = pl.u;
}

__global__ void repack_wx0b(const float* __restrict__ Wx0, const float* __restrict__ b0) {
    int n = blockIdx.x;            // n = h*4+g
    int g = n & 3, h = n >> 2;
    const float* src = Wx0 + (size_t)(g * HH + h) * IDIM;
    for (int i = threadIdx.x; i < IDIM; i += blockDim.x) {
        __nv_bfloat16 hh, ll; split_bf(src[i], hh, ll);
        size_t off = BW_OFF(n, i);
        *(__nv_bfloat16*)((char*)g_Bwh + off) = hh;
        *(__nv_bfloat16*)((char*)g_Bwl + off) = ll;
    }
    if (threadIdx.x == 0) g_b0r[n] = b0[g * HH + h];
}

__global__ void repack_w0(const float* __restrict__ Uh0, const float* __restrict__ Vc0) {
    int n = blockIdx.x;
    int g = n & 3, h = n >> 2;
    const float* u = Uh0 + (size_t)(g * HH + h) * HH;
    for (int k = threadIdx.x; k < HH; k += blockDim.x) {
        __nv_bfloat16 hh, ll; split_bf(u[k], hh, ll);
        size_t off = W0_OFF(n, k);
        *(__nv_bfloat16*)((char*)g_W0h + off) = hh;
        *(__nv_bfloat16*)((char*)g_W0l + off) = ll;
    }
    int vg = (g == 0) ? 0 : (g == 1) ? 1 : (g == 3) ? 2 : -1;   // Vc stacks [i,f,o]
    const float* v = (vg >= 0) ? (Vc0 + (size_t)(vg * HH + h) * HH) : 0;
    for (int k = threadIdx.x; k < HH; k += blockDim.x) {
        float val = (vg >= 0) ? v[k] : 0.0f;
        __nv_bfloat16 hh, ll; split_bf(val, hh, ll);
        size_t off = W0_OFF(n, HH + k);
        *(__nv_bfloat16*)((char*)g_W0h + off) = hh;
        *(__nv_bfloat16*)((char*)g_W0l + off) = ll;
    }
}

__global__ void repack_w1(const float* __restrict__ Wx1, const float* __restrict__ Uh1,
                          const float* __restrict__ Vc1, const float* __restrict__ b1) {
    int n = blockIdx.x;
    int g = n & 3, h = n >> 2;
    const float* wx = Wx1 + (size_t)(g * HH + h) * HH;
    const float* uh = Uh1 + (size_t)(g * HH + h) * HH;
    for (int k = threadIdx.x; k < HH; k += blockDim.x) {
        __nv_bfloat16 hh, ll;
        split_bf(wx[k], hh, ll);
        size_t off = W1_OFF(n, k);
        *(__nv_bfloat16*)((char*)g_W1h + off) = hh;
        *(__nv_bfloat16*)((char*)g_W1l + off) = ll;
        split_bf(uh[k], hh, ll);
        off = W1_OFF(n, HH + k);
        *(__nv_bfloat16*)((char*)g_W1h + off) = hh;
        *(__nv_bfloat16*)((char*)g_W1l + off) = ll;
    }
    int vg = (g == 0) ? 0 : (g == 1) ? 1 : (g == 3) ? 2 : -1;
    const float* v = (vg >= 0) ? (Vc1 + (size_t)(vg * HH + h) * HH) : 0;
    for (int k = threadIdx.x; k < HH; k += blockDim.x) {
        float val = (vg >= 0) ? v[k] : 0.0f;
        __nv_bfloat16 hh, ll; split_bf(val, hh, ll);
        size_t off = W1_OFF(n, 2 * HH + k);
        *(__nv_bfloat16*)((char*)g_W1h + off) = hh;
        *(__nv_bfloat16*)((char*)g_W1l + off) = ll;
    }
    if (threadIdx.x == 0) g_b1r[n] = b1[g * HH + h];
}

__global__ void init_state(const float* __restrict__ h0, const float* __restrict__ c0) {
    int idx = blockIdx.x * blockDim.x + threadIdx.x;   // B*H
    if (idx == 0) g_bar = 0u;
    int b = idx >> 10, h = idx & 1023;
    __nv_bfloat16 hh, ll;
    float v;
    size_t off;
    v = h0[b * HH + h];
    split_bf(v, hh, ll);
    off = ST_OFF(h, b);
    *(__nv_bfloat16*)((char*)g_S0h + off) = hh;
    *(__nv_bfloat16*)((char*)g_S0l + off) = ll;
    v = c0[b * HH + h];
    g_C0[idx] = v;
    split_bf(v, hh, ll);
    off = ST_OFF(HH + h, b);
    *(__nv_bfloat16*)((char*)g_S0h + off) = hh;
    *(__nv_bfloat16*)((char*)g_S0l + off) = ll;
    v = h0[BB * HH + b * HH + h];
    split_bf(v, hh, ll);
    off = ST_OFF(HH + h, b);
    *(__nv_bfloat16*)((char*)g_S1h + off) = hh;
    *(__nv_bfloat16*)((char*)g_S1l + off) = ll;
    v = c0[BB * HH + b * HH + h];
    g_C1[idx] = v;
    split_bf(v, hh, ll);
    off = ST_OFF(2 * HH + h, b);
    *(__nv_bfloat16*)((char*)g_S1h + off) = hh;
    *(__nv_bfloat16*)((char*)g_S1l + off) = ll;
    off = ST_OFF(h, b);
    *(__nv_bfloat16*)((char*)g_S1h + off) = __float2bfloat16(0.0f);
    *(__nv_bfloat16*)((char*)g_S1l + off) = __float2bfloat16(0.0f);
}

// ---------------- phase A: XZ0 = x @ Wx0^T + b0 ----------------
// CTA 128x128, chunk=64 k. Stage 64KB: Ah|Al|Bh|Bl (16KB each), double-buffered.
#define XZ_STAGE 65536u
__global__ __launch_bounds__(256) void gemm_xz_mma() {
    extern __shared__ __align__(128) char dsm[];
    __shared__ __align__(8) unsigned long long mbars[2];
    const int tid = threadIdx.x;
    const int w = tid >> 5, l = tid & 31;
    const int wm = w & 3, wn = w >> 2;
    const int m0 = blockIdx.y * 128, n0 = blockIdx.x * 128;
    const uint32_t sb = smem_u32(dsm);
    const uint32_t mb0 = smem_u32(mbars);
    if (tid == 0) { mbar_init(mb0, 1); mbar_init(mb0 + 8, 1); }
    __syncthreads();

    const char* Ah = (const char*)g_Axh + ((size_t)blockIdx.y * 64) * 16384;
    const char* Al = (const char*)g_Axl + ((size_t)blockIdx.y * 64) * 16384;
    const char* Bh = (const char*)g_Bwh + ((size_t)blockIdx.x * 64) * 16384;
    const char* Bl = (const char*)g_Bwl + ((size_t)blockIdx.x * 64) * 16384;

    auto issue = [&](int kc) {
        int st = kc & 1;
        uint32_t d = sb + st * XZ_STAGE;
        uint32_t mb = mb0 + st * 8;
        mbar_expect(mb, XZ_STAGE);
        bulk_cp(d,         Ah + (size_t)kc * 16384, 16384, mb);
        bulk_cp(d + 16384, Al + (size_t)kc * 16384, 16384, mb);
        bulk_cp(d + 32768, Bh + (size_t)kc * 16384, 16384, mb);
        bulk_cp(d + 49152, Bl + (size_t)kc * 16384, 16384, mb);
    };
    if (tid == 0) { issue(0); issue(1); }

    float acc[2][8][4];
#pragma unroll
    for (int a = 0; a < 2; a++)
#pragma unroll
        for (int b = 0; b < 8; b++)
#pragma unroll
            for (int c = 0; c < 4; c++) acc[a][b][c] = 0.0f;

    unsigned pst[2] = {0, 0};
    for (int kc = 0; kc < 64; kc++) {
        const int st = kc & 1;
        const uint32_t stb = sb + st * XZ_STAGE;
        mbar_wait(mb0 + st * 8, pst[st] & 1); pst[st]++;
#pragma unroll
        for (int ks = 0; ks < 4; ks++) {
            const int kb = ks * 32;
            uint32_t ah[2][4], al[2][4];
#pragma unroll
            for (int mt = 0; mt < 2; mt++) {
                int row = wm * 32 + mt * 16 + (l & 15);
                uint32_t ra = stb + (uint32_t)(row * 128 + ((kb + ((l >> 4) << 4)) ^ ((row & 7) << 4)));
                ldsm_x4(ah[mt], ra);
                ldsm_x4(al[mt], ra + 16384);
            }
#pragma unroll
            for (int nt = 0; nt < 8; nt++) {
                int row = wn * 64 + nt * 8 + (l & 7);
                uint32_t rb = stb + 32768 +
                    (uint32_t)(row * 128 + ((kb + (((l >> 3) & 1) << 4)) ^ ((row & 7) << 4)));
                uint32_t bh[2], bl[2];
                ldsm_x2(bh, rb);
                ldsm_x2(bl, rb + 16384);
#pragma unroll
                for (int mt = 0; mt < 2; mt++) {
                    mma_bf16(acc[mt][nt], ah[mt], bh);
                    mma_bf16(acc[mt][nt], ah[mt], bl);
                    mma_bf16(acc[mt][nt], al[mt], bh);
                }
            }
        }
        __syncthreads();
        if (tid == 0 && kc + 2 < 64) issue(kc + 2);
    }

    const int r0 = l >> 2, cp2 = (l & 3) * 2;
#pragma unroll
    for (int mt = 0; mt < 2; mt++)
#pragma unroll
        for (int half = 0; half < 2; half++) {
            int gm = m0 + wm * 32 + mt * 16 + r0 + half * 8;
            int t = gm & (TT - 1), b = gm >> 7;          // gm = b*T + t
            float* dst = g_XZ0 + ((size_t)(t * BB + b) << 12);
#pragma unroll
            for (int nt = 0; nt < 8; nt++) {
                int gc = n0 + wn * 64 + nt * 8 + cp2;
                float2 v;
                v.x = acc[mt][nt][half * 2 + 0] + g_b0r[gc];
                v.y = acc[mt][nt][half * 2 + 1] + g_b0r[gc + 1];
                *(float2*)(dst + gc) = v;
            }
        }
}

// ---------------- persistent loop GEMM phase ----------------
// Stage 48KB: Ah(8K)|Al(8K)|Bh(16K)|Bl(16K), double-buffered.
#define LP_STAGE 49152u
template <int WHICH>
__device__ __forceinline__ void gemm_phase(int cta, int tid, uint32_t sb, uint32_t mb0,
                                           unsigned& p0, unsigned& p1) {
    constexpr int NKC = (WHICH ? K1 : K0) / 64;
    constexpr int NC  = NKC / KSPLIT;                    // 8 or 12
    const char* Sh = (const char*)(WHICH ? g_S1h : g_S0h);
    const char* Sl = (const char*)(WHICH ? g_S1l : g_S0l);
    const char* Wh = (const char*)(WHICH ? g_W1h : g_W0h);
    const char* Wl = (const char*)(WHICH ? g_W1l : g_W0l);
    const int w = tid >> 5, l = tid & 31;
    const int wm = w & 3, wn = w >> 2;
    const int nblk = cta & 31, kseg = cta >> 5;
    const int kc0 = kseg * NC;

    auto issue = [&](int kc) {
        int st = kc & 1;
        uint32_t d = sb + st * LP_STAGE;
        uint32_t mb = mb0 + st * 8;
        mbar_expect(mb, LP_STAGE);
        bulk_cp(d,         Sh + (size_t)(kc0 + kc) * 8192, 8192, mb);
        bulk_cp(d + 8192,  Sl + (size_t)(kc0 + kc) * 8192, 8192, mb);
        bulk_cp(d + 16384, Wh + ((size_t)nblk * NKC + kc0 + kc) * 16384, 16384, mb);
        bulk_cp(d + 32768, Wl + ((size_t)nblk * NKC + kc0 + kc) * 16384, 16384, mb);
    };
    if (tid == 0) { issue(0); issue(1); }

    float acc[8][4];
#pragma unroll
    for (int b = 0; b < 8; b++)
#pragma unroll
        for (int c = 0; c < 4; c++) acc[b][c] = 0.0f;

    for (int kc = 0; kc < NC; kc++) {
        const int st = kc & 1;
        const uint32_t stb = sb + st * LP_STAGE;
        unsigned& ps = st ? p1 : p0;
        mbar_wait(mb0 + st * 8, ps & 1); ps++;
#pragma unroll
        for (int ks = 0; ks < 4; ks++) {
            const int kb = ks * 32;
            uint32_t ah[4], al[4];
            int arow = wm * 16 + (l & 15);
            uint32_t ra = stb + (uint32_t)(arow * 128 + ((kb + ((l >> 4) << 4)) ^ ((arow & 7) << 4)));
            ldsm_x4(ah, ra);
            ldsm_x4(al, ra + 8192);
#pragma unroll
            for (int nt = 0; nt < 8; nt++) {
                int brow = wn * 64 + nt * 8 + (l & 7);
                uint32_t rb = stb + 16384 +
                    (uint32_t)(brow * 128 + ((kb + (((l >> 3) & 1) << 4)) ^ ((brow & 7) << 4)));
                uint32_t bh[2], bl[2];
                ldsm_x2(bh, rb);
                ldsm_x2(bl, rb + 16384);
                mma_bf16(acc[nt], ah, bh);
                mma_bf16(acc[nt], ah, bl);
                mma_bf16(acc[nt], al, bh);
            }
        }
        __syncthreads();
        if (tid == 0 && kc + 2 < NC) issue(kc + 2);
    }

    float* dst = g_P[kseg];
    const int r0 = l >> 2, cp2 = (l & 3) * 2;
#pragma unroll
    for (int half = 0; half < 2; half++) {
        int b = wm * 16 + r0 + half * 8;
#pragma unroll
        for (int nt = 0; nt < 8; nt++) {
            int gc = nblk * 128 + wn * 64 + nt * 8 + cp2;
            float2 v;
            v.x = acc[nt][half * 2 + 0];
            v.y = acc[nt][half * 2 + 1];
            *(float2*)(dst + ((size_t)b << 12) + gc) = v;
        }
    }
}

__global__ __launch_bounds__(256) void rnn_loop(float* __restrict__ out) {
    extern __shared__ __align__(128) char dsm[];
    __shared__ __align__(8) unsigned long long mbars[2];
    const int cta = blockIdx.x, tid = threadIdx.x;
    const uint32_t sb = smem_u32(dsm);
    const uint32_t mb0 = smem_u32(mbars);
    if (tid == 0) { mbar_init(mb0, 1); mbar_init(mb0 + 8, 1); }
    __syncthreads();

    const int gthread = cta * 256 + tid;       // 0..32767
    const int idx0 = gthread * 2;              // owns idx0, idx0+1 (same b, consecutive h)
    const int b = idx0 >> 10;
    const int h0i = idx0 & 1023;
    float cA[2] = { g_C0[idx0], g_C0[idx0 + 1] };
    float cB[2] = { g_C1[idx0], g_C1[idx0 + 1] };
    float* hn_base = out + (size_t)BB * TT * HH;
    float* cn_base = hn_base + 2 * BB * HH;
    unsigned int seq = 0;
    unsigned p0 = 0, p1 = 0;

    for (int t = 0; t < TT; t++) {
        gemm_phase<0>(cta, tid, sb, mb0, p0, p1);
        grid_sync(++seq * GRID_N);

        // ---- epi0 ----
        {
            float hn[2], cn[2];
#pragma unroll
            for (int j = 0; j < 2; j++) {
                int h = h0i + j, nb = h << 2;
                float4 z = *(const float4*)&g_XZ0[((size_t)(t * BB + b) << 12) + nb];
#pragma unroll
                for (int ks = 0; ks < KSPLIT; ks++) {
                    float4 pp = __ldcg((const float4*)&g_P[ks][((size_t)b << 12) + nb]);
                    z.x += pp.x; z.y += pp.y; z.z += pp.z; z.w += pp.w;
                }
                float ig = sig_(z.x), fg = sig_(z.y), gg = tanhf(z.z), og = sig_(z.w);
                cn[j] = fg * cA[j] + ig * gg;
                hn[j] = og * tanhf(cn[j]);
                cA[j] = cn[j];
            }
            __nv_bfloat16 h0h, h0l, h1h, h1l, c0h, c0l, c1h, c1l;
            split_bf(hn[0], h0h, h0l); split_bf(hn[1], h1h, h1l);
            split_bf(cn[0], c0h, c0l); split_bf(cn[1], c1h, c1l);
            uint32_t hp = pack_bf2(h0h, h1h), lp = pack_bf2(h0l, h1l);
            size_t off = ST_OFF(h0i, b);
            *(uint32_t*)((char*)g_S0h + off) = hp;
            *(uint32_t*)((char*)g_S0l + off) = lp;
            *(uint32_t*)((char*)g_S1h + off) = hp;     // ha feeds layer 1
            *(uint32_t*)((char*)g_S1l + off) = lp;
            off = ST_OFF(HH + h0i, b);
            *(uint32_t*)((char*)g_S0h + off) = pack_bf2(c0h, c1h);
            *(uint32_t*)((char*)g_S0l + off) = pack_bf2(c0l, c1l);
            if (t == TT - 1) {
                hn_base[b * HH + h0i] = hn[0]; hn_base[b * HH + h0i + 1] = hn[1];
                cn_base[b * HH + h0i] = cn[0]; cn_base[b * HH + h0i + 1] = cn[1];
            }
        }
        grid_sync(++seq * GRID_N);

        gemm_phase<1>(cta, tid, sb, mb0, p0, p1);
        grid_sync(++seq * GRID_N);

        // ---- epi1 ----
        {
            float hn[2], cn[2];
#pragma unroll
            for (int j = 0; j < 2; j++) {
                int h = h0i + j, nb = h << 2;
                float4 z = *(const float4*)&g_b1r[nb];
#pragma unroll
                for (int ks = 0; ks < KSPLIT; ks++) {
                    float4 pp = __ldcg((const float4*)&g_P[ks][((size_t)b << 12) + nb]);
                    z.x += pp.x; z.y += pp.y; z.z += pp.z; z.w += pp.w;
                }
                float ig = sig_(z.x), fg = sig_(z.y), gg = tanhf(z.z), og = sig_(z.w);
                cn[j] = fg * cB[j] + ig * gg;
                hn[j] = og * tanhf(cn[j]);
                cB[j] = cn[j];
            }
            __nv_bfloat16 h0h, h0l, h1h, h1l, c0h, c0l, c1h, c1l;
            split_bf(hn[0], h0h, h0l); split_bf(hn[1], h1h, h1l);
            split_bf(cn[0], c0h, c0l); split_bf(cn[1], c1h, c1l);
            size_t off = ST_OFF(HH + h0i, b);
            *(uint32_t*)((char*)g_S1h + off) = pack_bf2(h0h, h1h);
            *(uint32_t*)((char*)g_S1l + off) = pack_bf2(h0l, h1l);
            off = ST_OFF(2 * HH + h0i, b);
            *(uint32_t*)((char*)g_S1h + off) = pack_bf2(c0h, c1h);
            *(uint32_t*)((char*)g_S1l + off) = pack_bf2(c0l, c1l);
            float* op = out + ((size_t)b * TT + t) * HH + h0i;
            op[0] = hn[0]; op[1] = hn[1];
            if (t == TT - 1) {
                hn_base[BB * HH + b * HH + h0i] = hn[0]; hn_base[BB * HH + b * HH + h0i + 1] = hn[1];
                cn_base[BB * HH + b * HH + h0i] = cn[0]; cn_base[BB * HH + b * HH + h0i + 1] = cn[1];
            }
        }
        grid_sync(++seq * GRID_N);
    }
}

// ---------------- launch ----------------
extern "C" void kernel_launch(void* const* d_in, const int* in_sizes, int n_in,
                              void* d_out, int out_size) {
    (void)in_sizes; (void)n_in; (void)out_size;
    const float* x   = (const float*)d_in[0];
    const float* h0  = (const float*)d_in[1];
    const float* c0  = (const float*)d_in[2];
    const float* Wx0 = (const float*)d_in[3];
    const float* Uh0 = (const float*)d_in[4];
    const float* Vc0 = (const float*)d_in[5];
    const float* b0  = (const float*)d_in[6];
    const float* Wx1 = (const float*)d_in[7];
    const float* Uh1 = (const float*)d_in[8];
    const float* Vc1 = (const float*)d_in[9];
    const float* b1  = (const float*)d_in[10];
    float* out = (float*)d_out;

    cudaFuncSetAttribute(gemm_xz_mma, cudaFuncAttributeMaxDynamicSharedMemorySize, 2 * XZ_STAGE);
    cudaFuncSetAttribute(rnn_loop,    cudaFuncAttributeMaxDynamicSharedMemorySize, 2 * LP_STAGE);

    conv_x     <<<(BB * TT * IDIM) / (4 * 256), 256>>>(x);
    repack_wx0b<<<FOURH, 256>>>(Wx0, b0);
    repack_w0  <<<FOURH, 256>>>(Uh0, Vc0);
    repack_w1  <<<FOURH, 256>>>(Wx1, Uh1, Vc1, b1);
    init_state <<<(BB * HH) / 256, 256>>>(h0, c0);

    gemm_xz_mma<<<dim3(FOURH / 128, (BB * TT) / 128), 256, 2 * XZ_STAGE>>>();

    rnn_loop<<<GRID_N, 256, 2 * LP_STAGE>>>(out);
}